// round 5
// baseline (speedup 1.0000x reference)
#include <cuda_runtime.h>
#include <cstdint>
#include <cstddef>

// Problem dims
#define LNUM 4
#define BB 2
#define SSEQ 1024
#define DDIM 1024
#define HH 16
#define DKK 64
#define FFD 4096
#define MM (BB * SSEQ)   // 2048 rows

// ---------------------------------------------------------------------------
// Scratch buffers (device globals — no allocations allowed)
// ---------------------------------------------------------------------------
__device__ float g_q[MM * DDIM];
__device__ float g_k[MM * DDIM];
__device__ float g_v[MM * DDIM];
__device__ float g_a[MM * DDIM];
__device__ float g_x1[MM * DDIM];
__device__ float g_y[MM * DDIM];
__device__ float g_tmp[MM * DDIM];
__device__ float g_h[MM * DDIM];
__device__ float g_hid[MM * FFD];

// ---------------------------------------------------------------------------
// helpers
// ---------------------------------------------------------------------------
__device__ __forceinline__ float tf32r(float x) {
    uint32_t u;
    asm("cvt.rna.tf32.f32 %0, %1;" : "=r"(u) : "f"(x));
    return __uint_as_float(u);
}
__device__ __forceinline__ void mma_tf32(float c[4], const uint32_t a[4], const uint32_t b[2]) {
    asm volatile(
        "mma.sync.aligned.m16n8k8.row.col.f32.tf32.tf32.f32 "
        "{%0,%1,%2,%3}, {%4,%5,%6,%7}, {%8,%9}, {%0,%1,%2,%3};"
        : "+f"(c[0]), "+f"(c[1]), "+f"(c[2]), "+f"(c[3])
        : "r"(a[0]), "r"(a[1]), "r"(a[2]), "r"(a[3]), "r"(b[0]), "r"(b[1]));
}

// ---------------------------------------------------------------------------
// TF32 tensor-core GEMM (warp-level HMMA): C = A @ B + bias (+res)(+relu)
// HEADED: B element (k,n) at ((n>>6)*K + k)*64 + (n&63)  (weights (H,D,DK))
// else:   B row-major [K,N]
//
// CTA tile 128x128, K-chunk 32, 256 thr = 8 warps (2x4, each 64x32).
// Smem layout (per stage): A[128 rows][40 floats], B[128 n][40 floats],
// where the 32 k values of a chunk are stored as 16 adjacent PAIRS
// (k, k+4) per kstep:  float2 at [row][ (ks*4+q)*2 ] = (v[ks*8+q], v[ks*8+q+4]).
// => every mma fragment load is a single LDS.64, conflict-free.
// Rounding to tf32 (cvt.rna) happens in the loader (zero-mean error).
// Pipeline: reg-prefetch next chunk + double-buffered smem, 1 sync/chunk.
// M,N multiples of 128; K multiple of 32.
// ---------------------------------------------------------------------------
#define TM 128
#define TN 128
#define PITCH 40                          // floats per row (32 data + 8 pad)
#define STAGE_FLOATS (2 * 128 * PITCH)    // A + B = 10240 floats = 40KB
#define GEMM_SMEM_BYTES (2 * STAGE_FLOATS * 4)   // 80KB

template <bool HEADED, bool RELU, bool RESID>
__global__ __launch_bounds__(256, 2)
void tc_gemm(const float* __restrict__ A, const float* __restrict__ B,
             const float* __restrict__ bias, const float* __restrict__ R,
             float* __restrict__ C, int M, int N, int K)
{
    extern __shared__ float smf[];

    const int tid  = threadIdx.x;
    const int lane = tid & 31;
    const int warp = tid >> 5;
    const int warpM = (warp & 1) * 64;   // 2 warp-rows
    const int warpN = (warp >> 1) * 32;  // 4 warp-cols
    const int row_blk = blockIdx.y * TM;
    const int col_blk = blockIdx.x * TN;

    const int lg = lane >> 2;            // 0..7
    const int lt = lane & 3;             // 0..3

    // loader mapping: thread handles one row of A and one n-col of B,
    // covering 16 k values (half a chunk).
    const int ld_row = tid & 127;        // A row / B n (within tile)
    const int ld_kh  = tid >> 7;         // 0/1: which 16-k half

    float acc[4][4][4];
#pragma unroll
    for (int i = 0; i < 4; i++)
#pragma unroll
        for (int j = 0; j < 4; j++)
#pragma unroll
            for (int r = 0; r < 4; r++) acc[i][j][r] = 0.f;

    const int nchunk = K >> 5;

    float ar[16];   // prefetched A values (k-local ld_kh*16 + 0..15)
    float br[16];   // prefetched B values

    const float* Arow = A + (size_t)(row_blk + ld_row) * K + ld_kh * 16;
    const int ng = col_blk + ld_row;
    const float* Bbase;
    size_t bstride;  // stride between consecutive k for fixed n
    if (HEADED) {
        Bbase = B + ((size_t)(ng >> 6) * K + ld_kh * 16) * 64 + (ng & 63);
        bstride = 64;
    } else {
        Bbase = B + (size_t)(ld_kh * 16) * N + ng;
        bstride = (size_t)N;
    }

    auto ldg_chunk = [&](int i) {
        const float* ap = Arow + (size_t)i * 32;
#pragma unroll
        for (int qd = 0; qd < 4; qd++) {
            float4 v = *(const float4*)(ap + qd * 4);
            ar[qd * 4 + 0] = v.x; ar[qd * 4 + 1] = v.y;
            ar[qd * 4 + 2] = v.z; ar[qd * 4 + 3] = v.w;
        }
        const float* bp = Bbase + (size_t)i * 32 * bstride;
#pragma unroll
        for (int kk = 0; kk < 16; kk++)
            br[kk] = bp[(size_t)kk * bstride];
    };

    auto sts_chunk = [&](int s) {
        float* As = smf + s * STAGE_FLOATS;
        float* Bs = As + 128 * PITCH;
#pragma unroll
        for (int ks2 = 0; ks2 < 2; ks2++) {
#pragma unroll
            for (int q = 0; q < 4; q++) {
                const int p = (ld_kh * 2 + ks2) * 4 + q;
                float2 va = make_float2(tf32r(ar[ks2 * 8 + q]), tf32r(ar[ks2 * 8 + q + 4]));
                *(float2*)&As[ld_row * PITCH + p * 2] = va;
                float2 vb = make_float2(tf32r(br[ks2 * 8 + q]), tf32r(br[ks2 * 8 + q + 4]));
                *(float2*)&Bs[ld_row * PITCH + p * 2] = vb;
            }
        }
    };

    ldg_chunk(0);

    for (int i = 0; i < nchunk; i++) {
        const int s = i & 1;
        sts_chunk(s);
        __syncthreads();
        if (i + 1 < nchunk) ldg_chunk(i + 1);

        const float* As = smf + s * STAGE_FLOATS;
        const float* Bs = As + 128 * PITCH;
#pragma unroll
        for (int ks = 0; ks < 4; ks++) {
            const int pcol = (ks * 4 + lt) * 2;
            uint32_t afr[4][4];
#pragma unroll
            for (int ii = 0; ii < 4; ii++) {
                const int m0 = warpM + ii * 16 + lg;
                float2 lo = *(const float2*)&As[m0 * PITCH + pcol];
                float2 hi = *(const float2*)&As[(m0 + 8) * PITCH + pcol];
                afr[ii][0] = __float_as_uint(lo.x);
                afr[ii][1] = __float_as_uint(hi.x);
                afr[ii][2] = __float_as_uint(lo.y);
                afr[ii][3] = __float_as_uint(hi.y);
            }
            uint32_t bfr[4][2];
#pragma unroll
            for (int jj = 0; jj < 4; jj++) {
                const int n0 = warpN + jj * 8 + lg;
                float2 bv = *(const float2*)&Bs[n0 * PITCH + pcol];
                bfr[jj][0] = __float_as_uint(bv.x);
                bfr[jj][1] = __float_as_uint(bv.y);
            }
#pragma unroll
            for (int ii = 0; ii < 4; ii++)
#pragma unroll
                for (int jj = 0; jj < 4; jj++)
                    mma_tf32(acc[ii][jj], afr[ii], bfr[jj]);
        }
        __syncthreads();
    }

    // Epilogue: c0,c1 at (row, 2*lt..+1); c2,c3 at row+8.
#pragma unroll
    for (int i = 0; i < 4; i++) {
#pragma unroll
        for (int j = 0; j < 4; j++) {
            int r0 = row_blk + warpM + i * 16 + lg;
            int c0 = col_blk + warpN + j * 8 + 2 * lt;
            float bv0 = bias[c0], bv1 = bias[c0 + 1];
            float v0 = acc[i][j][0] + bv0;
            float v1 = acc[i][j][1] + bv1;
            float v2 = acc[i][j][2] + bv0;
            float v3 = acc[i][j][3] + bv1;
            if (RESID) {
                const float2 r0v = *(const float2*)&R[(size_t)r0 * N + c0];
                const float2 r1v = *(const float2*)&R[(size_t)(r0 + 8) * N + c0];
                v0 += r0v.x; v1 += r0v.y; v2 += r1v.x; v3 += r1v.y;
            }
            if (RELU) {
                v0 = fmaxf(v0, 0.f); v1 = fmaxf(v1, 0.f);
                v2 = fmaxf(v2, 0.f); v3 = fmaxf(v3, 0.f);
            }
            *(float2*)&C[(size_t)r0 * N + c0]       = make_float2(v0, v1);
            *(float2*)&C[(size_t)(r0 + 8) * N + c0] = make_float2(v2, v3);
        }
    }
}

// ---------------------------------------------------------------------------
// Flash attention: q,k,v in (B, S, H*DK) concat layout; out in same layout.
// One CTA per (b, h, 64-row q tile). Online softmax over kv tiles of 64.
// kv length = *maskp (attn1) or S (maskp == nullptr).
// ---------------------------------------------------------------------------
#define AP 65   // pitch for transposed 64x64 tiles
#define VP 68   // pitch for row-major V tile (float4-aligned)
#define ATTN_SMEM_FLOATS (3 * 64 * AP + 64 * VP + 3 * 64)
#define ATTN_SMEM_BYTES (ATTN_SMEM_FLOATS * 4)

__global__ __launch_bounds__(256)
void attn_kernel(const float* __restrict__ q, const float* __restrict__ k,
                 const float* __restrict__ v, float* __restrict__ out,
                 const int* __restrict__ maskp)
{
    extern __shared__ float sm[];
    float* Qs  = sm;                  // [64][AP] transposed: Qs[d*AP + r]
    float* Ks  = Qs + 64 * AP;        // [64][AP] transposed: Ks[d*AP + c]
    float* Ps  = Ks + 64 * AP;        // [64][AP] row-major scores/probs
    float* Vs  = Ps + 64 * AP;        // [64][VP] row-major: Vs[c*VP + d]
    float* mrow = Vs + 64 * VP;       // [64]
    float* lrow = mrow + 64;          // [64]
    float* srow = lrow + 64;          // [64]

    const int tid = threadIdx.x;
    const int tx = tid & 15;          // col group
    const int ty = tid >> 4;          // row group
    const int qt = blockIdx.x;
    const int h  = blockIdx.y;
    const int b  = blockIdx.z;

    int kvlen = maskp ? *maskp : SSEQ;
    if (kvlen > SSEQ) kvlen = SSEQ;
    if (kvlen < 1) kvlen = 1;

    const float* qb = q + ((size_t)(b * SSEQ) + qt * 64) * DDIM + h * DKK;
    const float* kb = k + (size_t)(b * SSEQ) * DDIM + h * DKK;
    const float* vb = v + (size_t)(b * SSEQ) * DDIM + h * DKK;

    // load Q tile (transposed)
#pragma unroll
    for (int c = 0; c < 4; c++) {
        int idx = tid + c * 256;
        int r = idx >> 4;
        int d0 = (idx & 15) * 4;
        float4 t = *(const float4*)&qb[(size_t)r * DDIM + d0];
        Qs[(d0 + 0) * AP + r] = t.x;
        Qs[(d0 + 1) * AP + r] = t.y;
        Qs[(d0 + 2) * AP + r] = t.z;
        Qs[(d0 + 3) * AP + r] = t.w;
    }
    if (tid < 64) { mrow[tid] = -1e30f; lrow[tid] = 0.f; }

    float O[4][4];
#pragma unroll
    for (int i = 0; i < 4; i++)
#pragma unroll
        for (int j = 0; j < 4; j++) O[i][j] = 0.f;

    const int nt = (kvlen + 63) >> 6;
    for (int t = 0; t < nt; t++) {
        __syncthreads();   // previous-iteration consumers of Ks/Vs done
        const float* kt = kb + (size_t)(t * 64) * DDIM;
        const float* vt = vb + (size_t)(t * 64) * DDIM;
#pragma unroll
        for (int c = 0; c < 4; c++) {
            int idx = tid + c * 256;
            int r = idx >> 4;
            int d0 = (idx & 15) * 4;
            float4 tk = *(const float4*)&kt[(size_t)r * DDIM + d0];
            Ks[(d0 + 0) * AP + r] = tk.x;
            Ks[(d0 + 1) * AP + r] = tk.y;
            Ks[(d0 + 2) * AP + r] = tk.z;
            Ks[(d0 + 3) * AP + r] = tk.w;
            float4 tv = *(const float4*)&vt[(size_t)r * DDIM + d0];
            *(float4*)&Vs[r * VP + d0] = tv;
        }
        __syncthreads();

        // scores: s = (Q K^T) * 1/sqrt(64)
        float sacc[4][4];
#pragma unroll
        for (int i = 0; i < 4; i++)
#pragma unroll
            for (int j = 0; j < 4; j++) sacc[i][j] = 0.f;
#pragma unroll 8
        for (int d = 0; d < 64; d++) {
            float aq[4], bk[4];
#pragma unroll
            for (int i = 0; i < 4; i++) aq[i] = Qs[d * AP + ty * 4 + i];
#pragma unroll
            for (int j = 0; j < 4; j++) bk[j] = Ks[d * AP + tx * 4 + j];
#pragma unroll
            for (int i = 0; i < 4; i++)
#pragma unroll
                for (int j = 0; j < 4; j++) sacc[i][j] += aq[i] * bk[j];
        }
        const int cbase = t * 64 + tx * 4;
#pragma unroll
        for (int i = 0; i < 4; i++)
#pragma unroll
            for (int j = 0; j < 4; j++) {
                float val = (cbase + j < kvlen) ? sacc[i][j] * 0.125f : -1e30f;
                Ps[(ty * 4 + i) * AP + tx * 4 + j] = val;
            }
        __syncthreads();

        // per-row online softmax (one thread per row)
        if (tid < 64) {
            float mo = mrow[tid];
            float mt = -1e30f;
            float* pr = &Ps[tid * AP];
#pragma unroll 8
            for (int c = 0; c < 64; c++) mt = fmaxf(mt, pr[c]);
            float mn = fmaxf(mo, mt);
            float sc = __expf(mo - mn);
            float sum = 0.f;
#pragma unroll 8
            for (int c = 0; c < 64; c++) {
                float p = __expf(pr[c] - mn);
                pr[c] = p;
                sum += p;
            }
            lrow[tid] = lrow[tid] * sc + sum;
            mrow[tid] = mn;
            srow[tid] = sc;
        }
        __syncthreads();

        // rescale O, accumulate O += P @ V
        float sci[4];
#pragma unroll
        for (int i = 0; i < 4; i++) sci[i] = srow[ty * 4 + i];
#pragma unroll
        for (int i = 0; i < 4; i++)
#pragma unroll
            for (int j = 0; j < 4; j++) O[i][j] *= sci[i];
#pragma unroll 8
        for (int c = 0; c < 64; c++) {
            float pv[4];
#pragma unroll
            for (int i = 0; i < 4; i++) pv[i] = Ps[(ty * 4 + i) * AP + c];
            float4 vv = *(const float4*)&Vs[c * VP + tx * 4];
#pragma unroll
            for (int i = 0; i < 4; i++) {
                O[i][0] += pv[i] * vv.x;
                O[i][1] += pv[i] * vv.y;
                O[i][2] += pv[i] * vv.z;
                O[i][3] += pv[i] * vv.w;
            }
        }
    }
    __syncthreads();

    float* ob = out + ((size_t)(b * SSEQ) + qt * 64) * DDIM + h * DKK;
#pragma unroll
    for (int i = 0; i < 4; i++) {
        float inv = 1.f / lrow[ty * 4 + i];
#pragma unroll
        for (int j = 0; j < 4; j++)
            ob[(size_t)(ty * 4 + i) * DDIM + tx * 4 + j] = O[i][j] * inv;
    }
}

// ---------------------------------------------------------------------------
// BatchNorm over axes (B, D) per s index (channel axis = 1, S==D==1024).
// ---------------------------------------------------------------------------
__global__ __launch_bounds__(256)
void bn_kernel(const float* __restrict__ in, const float* __restrict__ g,
               const float* __restrict__ be, float* __restrict__ out)
{
    __shared__ float s_sum[256];
    __shared__ float s_sq[256];
    __shared__ float s_mean, s_rs;

    const int s = blockIdx.x;
    const int tid = threadIdx.x;

    float sum = 0.f, sq = 0.f;
#pragma unroll
    for (int b = 0; b < BB; b++) {
        const float* row = in + ((size_t)b * SSEQ + s) * DDIM;
        for (int d = tid; d < DDIM; d += 256) {
            float x = row[d];
            sum += x;
            sq += x * x;
        }
    }
    s_sum[tid] = sum;
    s_sq[tid] = sq;
    __syncthreads();
    for (int o = 128; o > 0; o >>= 1) {
        if (tid < o) { s_sum[tid] += s_sum[tid + o]; s_sq[tid] += s_sq[tid + o]; }
        __syncthreads();
    }
    if (tid == 0) {
        const float inv_n = 1.f / (BB * DDIM);
        float mean = s_sum[0] * inv_n;
        float var = s_sq[0] * inv_n - mean * mean;
        s_mean = mean;
        s_rs = rsqrtf(var + 1e-5f);
    }
    __syncthreads();
    const float gg = g[s], bb2 = be[s], mean = s_mean, rs = s_rs;
#pragma unroll
    for (int b = 0; b < BB; b++) {
        const float* row = in + ((size_t)b * SSEQ + s) * DDIM;
        float* orow = out + ((size_t)b * SSEQ + s) * DDIM;
        for (int d = tid; d < DDIM; d += 256) {
            orow[d] = (row[d] - mean) * rs * gg + bb2;
        }
    }
}

// ---------------------------------------------------------------------------
// Host orchestration
// ---------------------------------------------------------------------------
extern "C" void kernel_launch(void* const* d_in, const int* in_sizes, int n_in,
                              void* d_out, int out_size)
{
    const float* x   = (const float*)d_in[0];
    const float* Wq1 = (const float*)d_in[1];
    const float* bq1 = (const float*)d_in[2];
    const float* Wk1 = (const float*)d_in[3];
    const float* bk1 = (const float*)d_in[4];
    const float* Wv1 = (const float*)d_in[5];
    const float* bv1 = (const float*)d_in[6];
    const float* Wo1 = (const float*)d_in[7];
    const float* bo1 = (const float*)d_in[8];
    const float* Wq2 = (const float*)d_in[9];
    const float* bq2 = (const float*)d_in[10];
    const float* Wk2 = (const float*)d_in[11];
    const float* bk2 = (const float*)d_in[12];
    const float* Wv2 = (const float*)d_in[13];
    const float* bv2 = (const float*)d_in[14];
    const float* Wo2 = (const float*)d_in[15];
    const float* bo2 = (const float*)d_in[16];
    const float* g1  = (const float*)d_in[17];
    const float* be1 = (const float*)d_in[18];
    const float* g2  = (const float*)d_in[19];
    const float* be2 = (const float*)d_in[20];
    const float* g3  = (const float*)d_in[21];
    const float* be3 = (const float*)d_in[22];
    const float* W1  = (const float*)d_in[23];
    const float* bf1 = (const float*)d_in[24];
    const float* W2  = (const float*)d_in[25];
    const float* bf2 = (const float*)d_in[26];
    const int*   maskp = (const int*)d_in[27];

    float *q, *k, *v, *a, *x1, *y, *tmp, *h, *hid;
    cudaGetSymbolAddress((void**)&q,   g_q);
    cudaGetSymbolAddress((void**)&k,   g_k);
    cudaGetSymbolAddress((void**)&v,   g_v);
    cudaGetSymbolAddress((void**)&a,   g_a);
    cudaGetSymbolAddress((void**)&x1,  g_x1);
    cudaGetSymbolAddress((void**)&y,   g_y);
    cudaGetSymbolAddress((void**)&tmp, g_tmp);
    cudaGetSymbolAddress((void**)&h,   g_h);
    cudaGetSymbolAddress((void**)&hid, g_hid);

    cudaFuncSetAttribute(attn_kernel, cudaFuncAttributeMaxDynamicSharedMemorySize,
                         ATTN_SMEM_BYTES);
    cudaFuncSetAttribute(tc_gemm<true, false, false>,
                         cudaFuncAttributeMaxDynamicSharedMemorySize, GEMM_SMEM_BYTES);
    cudaFuncSetAttribute(tc_gemm<false, false, true>,
                         cudaFuncAttributeMaxDynamicSharedMemorySize, GEMM_SMEM_BYTES);
    cudaFuncSetAttribute(tc_gemm<false, true, false>,
                         cudaFuncAttributeMaxDynamicSharedMemorySize, GEMM_SMEM_BYTES);

    const dim3 blk(256);
    const dim3 gD(DDIM / TN, MM / TM);     // 8 x 16  (N=1024)
    const dim3 gF(FFD / TN, MM / TM);      // 32 x 16 (N=4096)
    const dim3 gAttn(SSEQ / 64, HH, BB);   // 16 x 16 x 2

    const float* hin = x;
    for (int l = 0; l < LNUM; l++) {
        const size_t wOff  = (size_t)l * HH * DDIM * DKK;   // QKV weights
        const size_t bOff  = (size_t)l * HH * DKK;          // QKV biases (1024)
        const size_t woOff = (size_t)l * DDIM * DDIM;       // Wo
        const size_t dOff  = (size_t)l * DDIM;              // per-D vectors
        const size_t w1Off = (size_t)l * DDIM * FFD;
        const size_t f1Off = (size_t)l * FFD;
        const size_t w2Off = (size_t)l * FFD * DDIM;

        // ---- masked self-attention ----
        tc_gemm<true, false, false><<<gD, blk, GEMM_SMEM_BYTES>>>(hin, Wq1 + wOff, bq1 + bOff, nullptr, q, MM, DDIM, DDIM);
        tc_gemm<true, false, false><<<gD, blk, GEMM_SMEM_BYTES>>>(hin, Wk1 + wOff, bk1 + bOff, nullptr, k, MM, DDIM, DDIM);
        tc_gemm<true, false, false><<<gD, blk, GEMM_SMEM_BYTES>>>(hin, Wv1 + wOff, bv1 + bOff, nullptr, v, MM, DDIM, DDIM);
        attn_kernel<<<gAttn, blk, ATTN_SMEM_BYTES>>>(q, k, v, a, maskp);
        tc_gemm<false, false, true><<<gD, blk, GEMM_SMEM_BYTES>>>(a, Wo1 + woOff, bo1 + dOff, hin, tmp, MM, DDIM, DDIM);
        bn_kernel<<<SSEQ, blk>>>(tmp, g1 + dOff, be1 + dOff, x1);

        // ---- second (unmasked) self-attention; residual from block input ----
        tc_gemm<true, false, false><<<gD, blk, GEMM_SMEM_BYTES>>>(x1, Wq2 + wOff, bq2 + bOff, nullptr, q, MM, DDIM, DDIM);
        tc_gemm<true, false, false><<<gD, blk, GEMM_SMEM_BYTES>>>(x1, Wk2 + wOff, bk2 + bOff, nullptr, k, MM, DDIM, DDIM);
        tc_gemm<true, false, false><<<gD, blk, GEMM_SMEM_BYTES>>>(x1, Wv2 + wOff, bv2 + bOff, nullptr, v, MM, DDIM, DDIM);
        attn_kernel<<<gAttn, blk, ATTN_SMEM_BYTES>>>(q, k, v, a, nullptr);
        tc_gemm<false, false, true><<<gD, blk, GEMM_SMEM_BYTES>>>(a, Wo2 + woOff, bo2 + dOff, hin, tmp, MM, DDIM, DDIM);
        bn_kernel<<<SSEQ, blk>>>(tmp, g2 + dOff, be2 + dOff, y);

        // ---- FFN; residual from x1 ----
        tc_gemm<false, true, false><<<gF, blk, GEMM_SMEM_BYTES>>>(y, W1 + w1Off, bf1 + f1Off, nullptr, hid, MM, FFD, DDIM);
        tc_gemm<false, false, true><<<gD, blk, GEMM_SMEM_BYTES>>>(hid, W2 + w2Off, bf2 + dOff, x1, tmp, MM, DDIM, FFD);

        float* dst = (l == LNUM - 1) ? (float*)d_out : h;
        bn_kernel<<<SSEQ, blk>>>(tmp, g3 + dOff, be3 + dOff, dst);
        hin = h;
    }
}

// round 7
// speedup vs baseline: 1.3093x; 1.3093x over previous
#include <cuda_runtime.h>
#include <cstdint>
#include <cstddef>

// Problem dims
#define LNUM 4
#define BB 2
#define SSEQ 1024
#define DDIM 1024
#define HH 16
#define DKK 64
#define FFD 4096
#define MM (BB * SSEQ)   // 2048 rows

// ---------------------------------------------------------------------------
// Scratch buffers (device globals — no allocations allowed)
// ---------------------------------------------------------------------------
__device__ float g_q[MM * DDIM];
__device__ float g_k[MM * DDIM];
__device__ float g_v[MM * DDIM];
__device__ float g_a[MM * DDIM];
__device__ float g_x1[MM * DDIM];
__device__ float g_y[MM * DDIM];
__device__ float g_tmp[MM * DDIM];
__device__ float g_h[MM * DDIM];
__device__ float g_hid[MM * FFD];

// tf32-pre-rounded weights / input
#define QKVW (LNUM * HH * DDIM * DKK)    // 4M
#define OW   (LNUM * DDIM * DDIM)        // 4M
#define W1SZ (LNUM * DDIM * FFD)         // 16M
__device__ float g_xr[MM * DDIM];
__device__ float g_wq1[QKVW];
__device__ float g_wk1[QKVW];
__device__ float g_wv1[QKVW];
__device__ float g_wo1[OW];
__device__ float g_wq2[QKVW];
__device__ float g_wk2[QKVW];
__device__ float g_wv2[QKVW];
__device__ float g_wo2[OW];
__device__ float g_w1r[W1SZ];
__device__ float g_w2r[W1SZ];

// ---------------------------------------------------------------------------
// helpers
// ---------------------------------------------------------------------------
__device__ __forceinline__ void cp_async16(uint32_t smem_dst, const void* gsrc) {
    asm volatile("cp.async.cg.shared.global [%0], [%1], 16;" :: "r"(smem_dst), "l"(gsrc));
}
__device__ __forceinline__ void cp_commit() {
    asm volatile("cp.async.commit_group;");
}
__device__ __forceinline__ float tf32r(float x) {
    uint32_t u;
    asm("cvt.rna.tf32.f32 %0, %1;" : "=r"(u) : "f"(x));
    return __uint_as_float(u);
}
__device__ __forceinline__ void mma_tf32(float c[4], const uint32_t a[4], const uint32_t b[2]) {
    asm volatile(
        "mma.sync.aligned.m16n8k8.row.col.f32.tf32.tf32.f32 "
        "{%0,%1,%2,%3}, {%4,%5,%6,%7}, {%8,%9}, {%0,%1,%2,%3};"
        : "+f"(c[0]), "+f"(c[1]), "+f"(c[2]), "+f"(c[3])
        : "r"(a[0]), "r"(a[1]), "r"(a[2]), "r"(a[3]), "r"(b[0]), "r"(b[1]));
}

// ---------------------------------------------------------------------------
// Pre-round an array to tf32 (rna) — grid-stride, float4
// ---------------------------------------------------------------------------
__global__ __launch_bounds__(256)
void round_kernel(const float* __restrict__ in, float* __restrict__ out, int n4)
{
    for (int i = blockIdx.x * blockDim.x + threadIdx.x; i < n4; i += gridDim.x * blockDim.x) {
        float4 v = ((const float4*)in)[i];
        v.x = tf32r(v.x); v.y = tf32r(v.y); v.z = tf32r(v.z); v.w = tf32r(v.w);
        ((float4*)out)[i] = v;
    }
}

// ---------------------------------------------------------------------------
// TF32 tensor-core GEMM: C[M,N] = A[M,K] @ B + bias (+ residual) (+ relu)
// Inputs A, B MUST already be tf32-rounded (hardware truncation is a no-op).
// HEADED: B element (k,n) at ((n>>6)*K + k)*64 + (n&63)  (weights (H,D,DK))
// else:   B row-major [K,N]
// CTA tile 128x128, K-chunk 32, 256 threads = 8 warps (2x4 of 64x32 each),
// m16n8k8 tf32 atoms, 2-stage cp.async double buffering.
// M,N multiples of 128; K multiple of 32 (holds for all our shapes).
// ---------------------------------------------------------------------------
#define GEMM_SMEM_FLOATS (2 * 128 * 36 + 2 * 32 * 132)
#define GEMM_SMEM_BYTES (GEMM_SMEM_FLOATS * 4)

template <bool HEADED, bool RELU, bool RESID, bool ROUND>
__global__ __launch_bounds__(256, 2)
void tgemm_kernel(const float* __restrict__ A, const float* __restrict__ B,
                  const float* __restrict__ bias, const float* __restrict__ R,
                  float* __restrict__ C, int M, int N, int K)
{
    extern __shared__ float smf[];
    float (*As)[128][36]  = (float(*)[128][36])smf;                  // [2][128][36]
    float (*Bs)[32][132]  = (float(*)[32][132])(smf + 2 * 128 * 36); // [2][32][132]

    const int tid  = threadIdx.x;
    const int lane = tid & 31;
    const int warp = tid >> 5;
    const int warpM = (warp & 1) * 64;   // 2 warp-rows
    const int warpN = (warp >> 1) * 32;  // 4 warp-cols
    const int row_blk = blockIdx.y * 128;
    const int col_blk = blockIdx.x * 128;

    // loader mapping
    const int a_r = tid >> 3;          // 0..31
    const int a_c = (tid & 7) * 4;     // 0,4,..28
    const int b_k = tid >> 5;          // 0..7
    const int b_n = (tid & 31) * 4;    // 0..124

    const int lg = lane >> 2;          // groupID 0..7
    const int lt = lane & 3;           // thread-in-group 0..3

    float acc[4][4][4];
#pragma unroll
    for (int i = 0; i < 4; i++)
#pragma unroll
        for (int j = 0; j < 4; j++)
#pragma unroll
            for (int r = 0; r < 4; r++) acc[i][j][r] = 0.f;

    const int nk = K >> 5;

    auto prefetch = [&](int kc, int buf) {
        const float* Ag = A + (size_t)row_blk * K + kc * 32;
#pragma unroll
        for (int i = 0; i < 4; i++) {
            int r = a_r + i * 32;
            uint32_t dst = (uint32_t)__cvta_generic_to_shared(&As[buf][r][a_c]);
            cp_async16(dst, Ag + (size_t)r * K + a_c);
        }
#pragma unroll
        for (int i = 0; i < 4; i++) {
            int k = b_k + i * 8;
            uint32_t dst = (uint32_t)__cvta_generic_to_shared(&Bs[buf][k][b_n]);
            const float* src;
            if (HEADED) {
                int n = col_blk + b_n;
                src = B + ((size_t)(n >> 6) * K + kc * 32 + k) * 64 + (n & 63);
            } else {
                src = B + (size_t)(kc * 32 + k) * N + col_blk + b_n;
            }
            cp_async16(dst, src);
        }
    };

    prefetch(0, 0);
    cp_commit();

    for (int kc = 0; kc < nk; kc++) {
        if (kc + 1 < nk) {
            prefetch(kc + 1, (kc + 1) & 1);
            cp_commit();
            asm volatile("cp.async.wait_group 1;");
        } else {
            asm volatile("cp.async.wait_group 0;");
        }
        __syncthreads();

        const int buf = kc & 1;
#pragma unroll
        for (int ks = 0; ks < 4; ks++) {
            const int k0 = ks * 8;
            uint32_t afr[4][4];
#pragma unroll
            for (int i = 0; i < 4; i++) {
                int m = warpM + i * 16 + lg;
                afr[i][0] = __float_as_uint(As[buf][m][k0 + lt]);
                afr[i][1] = __float_as_uint(As[buf][m + 8][k0 + lt]);
                afr[i][2] = __float_as_uint(As[buf][m][k0 + lt + 4]);
                afr[i][3] = __float_as_uint(As[buf][m + 8][k0 + lt + 4]);
            }
            uint32_t bfr[4][2];
#pragma unroll
            for (int j = 0; j < 4; j++) {
                int n = warpN + j * 8 + lg;
                bfr[j][0] = __float_as_uint(Bs[buf][k0 + lt][n]);
                bfr[j][1] = __float_as_uint(Bs[buf][k0 + lt + 4][n]);
            }
#pragma unroll
            for (int i = 0; i < 4; i++)
#pragma unroll
                for (int j = 0; j < 4; j++)
                    mma_tf32(acc[i][j], afr[i], bfr[j]);
        }
        __syncthreads();
    }

    // Epilogue: c0,c1 at (row, 2*lt), (row, 2*lt+1); c2,c3 at row+8.
#pragma unroll
    for (int i = 0; i < 4; i++) {
#pragma unroll
        for (int j = 0; j < 4; j++) {
            int r0 = row_blk + warpM + i * 16 + lg;
            int c0 = col_blk + warpN + j * 8 + 2 * lt;
            float bv0 = bias[c0], bv1 = bias[c0 + 1];
            float v0 = acc[i][j][0] + bv0;
            float v1 = acc[i][j][1] + bv1;
            float v2 = acc[i][j][2] + bv0;
            float v3 = acc[i][j][3] + bv1;
            if (RESID) {
                const float2 r0v = *(const float2*)&R[(size_t)r0 * N + c0];
                const float2 r1v = *(const float2*)&R[(size_t)(r0 + 8) * N + c0];
                v0 += r0v.x; v1 += r0v.y; v2 += r1v.x; v3 += r1v.y;
            }
            if (RELU) {
                v0 = fmaxf(v0, 0.f); v1 = fmaxf(v1, 0.f);
                v2 = fmaxf(v2, 0.f); v3 = fmaxf(v3, 0.f);
            }
            if (ROUND) {
                v0 = tf32r(v0); v1 = tf32r(v1); v2 = tf32r(v2); v3 = tf32r(v3);
            }
            *(float2*)&C[(size_t)r0 * N + c0]       = make_float2(v0, v1);
            *(float2*)&C[(size_t)(r0 + 8) * N + c0] = make_float2(v2, v3);
        }
    }
}

// ---------------------------------------------------------------------------
// Flash attention: q,k,v in (B, S, H*DK) concat layout; out in same layout.
// Output is tf32-rounded (it always feeds a GEMM A-operand).
// One CTA per (b, h, 64-row q tile). Online softmax over kv tiles of 64.
// kv length = *maskp (attn1) or S (maskp == nullptr).
// ---------------------------------------------------------------------------
#define AP 65   // pitch for transposed 64x64 tiles
#define VP 68   // pitch for row-major V tile (float4-aligned)
#define ATTN_SMEM_FLOATS (3 * 64 * AP + 64 * VP + 3 * 64)
#define ATTN_SMEM_BYTES (ATTN_SMEM_FLOATS * 4)

__global__ __launch_bounds__(256)
void attn_kernel(const float* __restrict__ q, const float* __restrict__ k,
                 const float* __restrict__ v, float* __restrict__ out,
                 const int* __restrict__ maskp)
{
    extern __shared__ float sm[];
    float* Qs  = sm;                  // [64][AP] transposed: Qs[d*AP + r]
    float* Ks  = Qs + 64 * AP;        // [64][AP] transposed: Ks[d*AP + c]
    float* Ps  = Ks + 64 * AP;        // [64][AP] row-major scores/probs
    float* Vs  = Ps + 64 * AP;        // [64][VP] row-major: Vs[c*VP + d]
    float* mrow = Vs + 64 * VP;       // [64]
    float* lrow = mrow + 64;          // [64]
    float* srow = lrow + 64;          // [64]

    const int tid = threadIdx.x;
    const int tx = tid & 15;          // col group
    const int ty = tid >> 4;          // row group
    const int qt = blockIdx.x;
    const int h  = blockIdx.y;
    const int b  = blockIdx.z;

    int kvlen = maskp ? *maskp : SSEQ;
    if (kvlen > SSEQ) kvlen = SSEQ;
    if (kvlen < 1) kvlen = 1;

    const float* qb = q + ((size_t)(b * SSEQ) + qt * 64) * DDIM + h * DKK;
    const float* kb = k + (size_t)(b * SSEQ) * DDIM + h * DKK;
    const float* vb = v + (size_t)(b * SSEQ) * DDIM + h * DKK;

    // load Q tile (transposed)
#pragma unroll
    for (int c = 0; c < 4; c++) {
        int idx = tid + c * 256;
        int r = idx >> 4;
        int d0 = (idx & 15) * 4;
        float4 t = *(const float4*)&qb[(size_t)r * DDIM + d0];
        Qs[(d0 + 0) * AP + r] = t.x;
        Qs[(d0 + 1) * AP + r] = t.y;
        Qs[(d0 + 2) * AP + r] = t.z;
        Qs[(d0 + 3) * AP + r] = t.w;
    }
    if (tid < 64) { mrow[tid] = -1e30f; lrow[tid] = 0.f; }

    float O[4][4];
#pragma unroll
    for (int i = 0; i < 4; i++)
#pragma unroll
        for (int j = 0; j < 4; j++) O[i][j] = 0.f;

    const int nt = (kvlen + 63) >> 6;
    for (int t = 0; t < nt; t++) {
        __syncthreads();   // previous-iteration consumers of Ks/Vs done
        const float* kt = kb + (size_t)(t * 64) * DDIM;
        const float* vt = vb + (size_t)(t * 64) * DDIM;
#pragma unroll
        for (int c = 0; c < 4; c++) {
            int idx = tid + c * 256;
            int r = idx >> 4;
            int d0 = (idx & 15) * 4;
            float4 tk = *(const float4*)&kt[(size_t)r * DDIM + d0];
            Ks[(d0 + 0) * AP + r] = tk.x;
            Ks[(d0 + 1) * AP + r] = tk.y;
            Ks[(d0 + 2) * AP + r] = tk.z;
            Ks[(d0 + 3) * AP + r] = tk.w;
            float4 tv = *(const float4*)&vt[(size_t)r * DDIM + d0];
            *(float4*)&Vs[r * VP + d0] = tv;
        }
        __syncthreads();

        // scores: s = (Q K^T) * 1/sqrt(64)
        float sacc[4][4];
#pragma unroll
        for (int i = 0; i < 4; i++)
#pragma unroll
            for (int j = 0; j < 4; j++) sacc[i][j] = 0.f;
#pragma unroll 8
        for (int d = 0; d < 64; d++) {
            float aq[4], bk[4];
#pragma unroll
            for (int i = 0; i < 4; i++) aq[i] = Qs[d * AP + ty * 4 + i];
#pragma unroll
            for (int j = 0; j < 4; j++) bk[j] = Ks[d * AP + tx * 4 + j];
#pragma unroll
            for (int i = 0; i < 4; i++)
#pragma unroll
                for (int j = 0; j < 4; j++) sacc[i][j] += aq[i] * bk[j];
        }
        const int cbase = t * 64 + tx * 4;
#pragma unroll
        for (int i = 0; i < 4; i++)
#pragma unroll
            for (int j = 0; j < 4; j++) {
                float val = (cbase + j < kvlen) ? sacc[i][j] * 0.125f : -1e30f;
                Ps[(ty * 4 + i) * AP + tx * 4 + j] = val;
            }
        __syncthreads();

        // per-row online softmax (one thread per row)
        if (tid < 64) {
            float mo = mrow[tid];
            float mt = -1e30f;
            float* pr = &Ps[tid * AP];
#pragma unroll 8
            for (int c = 0; c < 64; c++) mt = fmaxf(mt, pr[c]);
            float mn = fmaxf(mo, mt);
            float sc = __expf(mo - mn);
            float sum = 0.f;
#pragma unroll 8
            for (int c = 0; c < 64; c++) {
                float p = __expf(pr[c] - mn);
                pr[c] = p;
                sum += p;
            }
            lrow[tid] = lrow[tid] * sc + sum;
            mrow[tid] = mn;
            srow[tid] = sc;
        }
        __syncthreads();

        // rescale O, accumulate O += P @ V
        float sci[4];
#pragma unroll
        for (int i = 0; i < 4; i++) sci[i] = srow[ty * 4 + i];
#pragma unroll
        for (int i = 0; i < 4; i++)
#pragma unroll
            for (int j = 0; j < 4; j++) O[i][j] *= sci[i];
#pragma unroll 8
        for (int c = 0; c < 64; c++) {
            float pv[4];
#pragma unroll
            for (int i = 0; i < 4; i++) pv[i] = Ps[(ty * 4 + i) * AP + c];
            float4 vv = *(const float4*)&Vs[c * VP + tx * 4];
#pragma unroll
            for (int i = 0; i < 4; i++) {
                O[i][0] += pv[i] * vv.x;
                O[i][1] += pv[i] * vv.y;
                O[i][2] += pv[i] * vv.z;
                O[i][3] += pv[i] * vv.w;
            }
        }
    }
    __syncthreads();

    float* ob = out + ((size_t)(b * SSEQ) + qt * 64) * DDIM + h * DKK;
#pragma unroll
    for (int i = 0; i < 4; i++) {
        float inv = 1.f / lrow[ty * 4 + i];
#pragma unroll
        for (int j = 0; j < 4; j++)
            ob[(size_t)(ty * 4 + i) * DDIM + tx * 4 + j] = tf32r(O[i][j] * inv);
    }
}

// ---------------------------------------------------------------------------
// BatchNorm over axes (B, D) per s index (channel axis = 1, S==D==1024).
// do_round: tf32-round the output (when it feeds a GEMM A-operand).
// ---------------------------------------------------------------------------
__global__ __launch_bounds__(256)
void bn_kernel(const float* __restrict__ in, const float* __restrict__ g,
               const float* __restrict__ be, float* __restrict__ out, int do_round)
{
    __shared__ float s_sum[256];
    __shared__ float s_sq[256];
    __shared__ float s_mean, s_rs;

    const int s = blockIdx.x;
    const int tid = threadIdx.x;

    float sum = 0.f, sq = 0.f;
#pragma unroll
    for (int b = 0; b < BB; b++) {
        const float* row = in + ((size_t)b * SSEQ + s) * DDIM;
        for (int d = tid; d < DDIM; d += 256) {
            float x = row[d];
            sum += x;
            sq += x * x;
        }
    }
    s_sum[tid] = sum;
    s_sq[tid] = sq;
    __syncthreads();
    for (int o = 128; o > 0; o >>= 1) {
        if (tid < o) { s_sum[tid] += s_sum[tid + o]; s_sq[tid] += s_sq[tid + o]; }
        __syncthreads();
    }
    if (tid == 0) {
        const float inv_n = 1.f / (BB * DDIM);
        float mean = s_sum[0] * inv_n;
        float var = s_sq[0] * inv_n - mean * mean;
        s_mean = mean;
        s_rs = rsqrtf(var + 1e-5f);
    }
    __syncthreads();
    const float gg = g[s], bb2 = be[s], mean = s_mean, rs = s_rs;
#pragma unroll
    for (int b = 0; b < BB; b++) {
        const float* row = in + ((size_t)b * SSEQ + s) * DDIM;
        float* orow = out + ((size_t)b * SSEQ + s) * DDIM;
        for (int d = tid; d < DDIM; d += 256) {
            float val = (row[d] - mean) * rs * gg + bb2;
            orow[d] = do_round ? tf32r(val) : val;
        }
    }
}

// ---------------------------------------------------------------------------
// Host orchestration
// ---------------------------------------------------------------------------
extern "C" void kernel_launch(void* const* d_in, const int* in_sizes, int n_in,
                              void* d_out, int out_size)
{
    const float* x   = (const float*)d_in[0];
    const float* Wq1 = (const float*)d_in[1];
    const float* bq1 = (const float*)d_in[2];
    const float* Wk1 = (const float*)d_in[3];
    const float* bk1 = (const float*)d_in[4];
    const float* Wv1 = (const float*)d_in[5];
    const float* bv1 = (const float*)d_in[6];
    const float* Wo1 = (const float*)d_in[7];
    const float* bo1 = (const float*)d_in[8];
    const float* Wq2 = (const float*)d_in[9];
    const float* bq2 = (const float*)d_in[10];
    const float* Wk2 = (const float*)d_in[11];
    const float* bk2 = (const float*)d_in[12];
    const float* Wv2 = (const float*)d_in[13];
    const float* bv2 = (const float*)d_in[14];
    const float* Wo2 = (const float*)d_in[15];
    const float* bo2 = (const float*)d_in[16];
    const float* g1  = (const float*)d_in[17];
    const float* be1 = (const float*)d_in[18];
    const float* g2  = (const float*)d_in[19];
    const float* be2 = (const float*)d_in[20];
    const float* g3  = (const float*)d_in[21];
    const float* be3 = (const float*)d_in[22];
    const float* W1  = (const float*)d_in[23];
    const float* bf1 = (const float*)d_in[24];
    const float* W2  = (const float*)d_in[25];
    const float* bf2 = (const float*)d_in[26];
    const int*   maskp = (const int*)d_in[27];

    float *q, *k, *v, *a, *x1, *y, *tmp, *h, *hid;
    float *xr, *wq1, *wk1, *wv1, *wo1, *wq2, *wk2, *wv2, *wo2, *w1r, *w2r;
    cudaGetSymbolAddress((void**)&q,   g_q);
    cudaGetSymbolAddress((void**)&k,   g_k);
    cudaGetSymbolAddress((void**)&v,   g_v);
    cudaGetSymbolAddress((void**)&a,   g_a);
    cudaGetSymbolAddress((void**)&x1,  g_x1);
    cudaGetSymbolAddress((void**)&y,   g_y);
    cudaGetSymbolAddress((void**)&tmp, g_tmp);
    cudaGetSymbolAddress((void**)&h,   g_h);
    cudaGetSymbolAddress((void**)&hid, g_hid);
    cudaGetSymbolAddress((void**)&xr,  g_xr);
    cudaGetSymbolAddress((void**)&wq1, g_wq1);
    cudaGetSymbolAddress((void**)&wk1, g_wk1);
    cudaGetSymbolAddress((void**)&wv1, g_wv1);
    cudaGetSymbolAddress((void**)&wo1, g_wo1);
    cudaGetSymbolAddress((void**)&wq2, g_wq2);
    cudaGetSymbolAddress((void**)&wk2, g_wk2);
    cudaGetSymbolAddress((void**)&wv2, g_wv2);
    cudaGetSymbolAddress((void**)&wo2, g_wo2);
    cudaGetSymbolAddress((void**)&w1r, g_w1r);
    cudaGetSymbolAddress((void**)&w2r, g_w2r);

    cudaFuncSetAttribute(attn_kernel, cudaFuncAttributeMaxDynamicSharedMemorySize,
                         ATTN_SMEM_BYTES);
    cudaFuncSetAttribute(tgemm_kernel<true, false, false, false>,
                         cudaFuncAttributeMaxDynamicSharedMemorySize, GEMM_SMEM_BYTES);
    cudaFuncSetAttribute(tgemm_kernel<false, false, true, false>,
                         cudaFuncAttributeMaxDynamicSharedMemorySize, GEMM_SMEM_BYTES);
    cudaFuncSetAttribute(tgemm_kernel<false, true, false, true>,
                         cudaFuncAttributeMaxDynamicSharedMemorySize, GEMM_SMEM_BYTES);

    // ---- pre-round weights + input to tf32 (rna) ----
    {
        const dim3 rb(256);
        round_kernel<<<512,  rb>>>(x,   xr,  (MM * DDIM) / 4);
        round_kernel<<<1024, rb>>>(Wq1, wq1, QKVW / 4);
        round_kernel<<<1024, rb>>>(Wk1, wk1, QKVW / 4);
        round_kernel<<<1024, rb>>>(Wv1, wv1, QKVW / 4);
        round_kernel<<<1024, rb>>>(Wo1, wo1, OW / 4);
        round_kernel<<<1024, rb>>>(Wq2, wq2, QKVW / 4);
        round_kernel<<<1024, rb>>>(Wk2, wk2, QKVW / 4);
        round_kernel<<<1024, rb>>>(Wv2, wv2, QKVW / 4);
        round_kernel<<<1024, rb>>>(Wo2, wo2, OW / 4);
        round_kernel<<<2048, rb>>>(W1,  w1r, W1SZ / 4);
        round_kernel<<<2048, rb>>>(W2,  w2r, W1SZ / 4);
    }

    const dim3 blk(256);
    const dim3 gD(DDIM / 128, MM / 128);   // 8 x 16  (N=1024)
    const dim3 gF(FFD / 128, MM / 128);    // 32 x 16 (N=4096)
    const dim3 gAttn(SSEQ / 64, HH, BB);   // 16 x 16 x 2

    const float* hin = xr;                 // rounded A-operand
    const float* hres = x;                 // residual (full precision for layer 0)
    for (int l = 0; l < LNUM; l++) {
        const size_t wOff  = (size_t)l * HH * DDIM * DKK;   // QKV weights
        const size_t bOff  = (size_t)l * HH * DKK;          // QKV biases (1024)
        const size_t woOff = (size_t)l * DDIM * DDIM;       // Wo
        const size_t dOff  = (size_t)l * DDIM;              // per-D vectors
        const size_t w1Off = (size_t)l * DDIM * FFD;
        const size_t f1Off = (size_t)l * FFD;
        const size_t w2Off = (size_t)l * FFD * DDIM;

        // ---- masked self-attention ----
        tgemm_kernel<true, false, false, false><<<gD, blk, GEMM_SMEM_BYTES>>>(hin, wq1 + wOff, bq1 + bOff, nullptr, q, MM, DDIM, DDIM);
        tgemm_kernel<true, false, false, false><<<gD, blk, GEMM_SMEM_BYTES>>>(hin, wk1 + wOff, bk1 + bOff, nullptr, k, MM, DDIM, DDIM);
        tgemm_kernel<true, false, false, false><<<gD, blk, GEMM_SMEM_BYTES>>>(hin, wv1 + wOff, bv1 + bOff, nullptr, v, MM, DDIM, DDIM);
        attn_kernel<<<gAttn, blk, ATTN_SMEM_BYTES>>>(q, k, v, a, maskp);
        tgemm_kernel<false, false, true, false><<<gD, blk, GEMM_SMEM_BYTES>>>(a, wo1 + woOff, bo1 + dOff, hres, tmp, MM, DDIM, DDIM);
        bn_kernel<<<SSEQ, blk>>>(tmp, g1 + dOff, be1 + dOff, x1, 1);

        // ---- second (unmasked) self-attention; residual from block input ----
        tgemm_kernel<true, false, false, false><<<gD, blk, GEMM_SMEM_BYTES>>>(x1, wq2 + wOff, bq2 + bOff, nullptr, q, MM, DDIM, DDIM);
        tgemm_kernel<true, false, false, false><<<gD, blk, GEMM_SMEM_BYTES>>>(x1, wk2 + wOff, bk2 + bOff, nullptr, k, MM, DDIM, DDIM);
        tgemm_kernel<true, false, false, false><<<gD, blk, GEMM_SMEM_BYTES>>>(x1, wv2 + wOff, bv2 + bOff, nullptr, v, MM, DDIM, DDIM);
        attn_kernel<<<gAttn, blk, ATTN_SMEM_BYTES>>>(q, k, v, a, nullptr);
        tgemm_kernel<false, false, true, false><<<gD, blk, GEMM_SMEM_BYTES>>>(a, wo2 + woOff, bo2 + dOff, hres, tmp, MM, DDIM, DDIM);
        bn_kernel<<<SSEQ, blk>>>(tmp, g2 + dOff, be2 + dOff, y, 1);

        // ---- FFN; residual from x1 ----
        tgemm_kernel<false, true, false, true><<<gF, blk, GEMM_SMEM_BYTES>>>(y, w1r + w1Off, bf1 + f1Off, nullptr, hid, MM, FFD, DDIM);
        tgemm_kernel<false, false, true, false><<<gD, blk, GEMM_SMEM_BYTES>>>(hid, w2r + w2Off, bf2 + dOff, x1, tmp, MM, DDIM, FFD);

        float* dst = (l == LNUM - 1) ? (float*)d_out : h;
        bn_kernel<<<SSEQ, blk>>>(tmp, g3 + dOff, be3 + dOff, dst, (l == LNUM - 1) ? 0 : 1);
        hin = h;
        hres = h;
    }
}

// round 8
// speedup vs baseline: 1.9041x; 1.4543x over previous
#include <cuda_runtime.h>
#include <cuda_fp16.h>
#include <cstdint>
#include <cstddef>

// Problem dims
#define LNUM 4
#define BB 2
#define SSEQ 1024
#define DDIM 1024
#define HH 16
#define DKK 64
#define FFD 4096
#define MM (BB * SSEQ)   // 2048 rows

// ---------------------------------------------------------------------------
// Scratch buffers (device globals — no allocations allowed)
// ---------------------------------------------------------------------------
__device__ float g_q[MM * DDIM];
__device__ float g_k[MM * DDIM];
__device__ float g_v[MM * DDIM];
__device__ float g_tmp[MM * DDIM];
__device__ float g_x1f[MM * DDIM];
__device__ float g_hf[MM * DDIM];

__device__ __half g_xh[MM * DDIM];
__device__ __half g_ah[MM * DDIM];
__device__ __half g_x1h[MM * DDIM];
__device__ __half g_yh[MM * DDIM];
__device__ __half g_hh[MM * DDIM];
__device__ __half g_hidh[MM * FFD];

#define QKVW (LNUM * HH * DDIM * DKK)    // 4M
#define OW   (LNUM * DDIM * DDIM)        // 4M
#define W1SZ (LNUM * DDIM * FFD)         // 16M
__device__ __half g_wq1[QKVW];
__device__ __half g_wk1[QKVW];
__device__ __half g_wv1[QKVW];
__device__ __half g_wo1[OW];
__device__ __half g_wq2[QKVW];
__device__ __half g_wk2[QKVW];
__device__ __half g_wv2[QKVW];
__device__ __half g_wo2[OW];
__device__ __half g_w1h[W1SZ];
__device__ __half g_w2h[W1SZ];

// ---------------------------------------------------------------------------
// helpers
// ---------------------------------------------------------------------------
__device__ __forceinline__ void cp_async16(uint32_t smem_dst, const void* gsrc) {
    asm volatile("cp.async.cg.shared.global [%0], [%1], 16;" :: "r"(smem_dst), "l"(gsrc));
}
__device__ __forceinline__ void cp_commit() {
    asm volatile("cp.async.commit_group;");
}
__device__ __forceinline__ void ldsm_x4(uint32_t r[4], uint32_t addr) {
    asm volatile("ldmatrix.sync.aligned.m8n8.x4.shared.b16 {%0,%1,%2,%3}, [%4];"
                 : "=r"(r[0]), "=r"(r[1]), "=r"(r[2]), "=r"(r[3]) : "r"(addr));
}
__device__ __forceinline__ void ldsm_x2_t(uint32_t r[2], uint32_t addr) {
    asm volatile("ldmatrix.sync.aligned.m8n8.x2.trans.shared.b16 {%0,%1}, [%2];"
                 : "=r"(r[0]), "=r"(r[1]) : "r"(addr));
}
__device__ __forceinline__ void mma_f16(float c[4], const uint32_t a[4], const uint32_t b[2]) {
    asm volatile(
        "mma.sync.aligned.m16n8k16.row.col.f32.f16.f16.f32 "
        "{%0,%1,%2,%3}, {%4,%5,%6,%7}, {%8,%9}, {%0,%1,%2,%3};"
        : "+f"(c[0]), "+f"(c[1]), "+f"(c[2]), "+f"(c[3])
        : "r"(a[0]), "r"(a[1]), "r"(a[2]), "r"(a[3]), "r"(b[0]), "r"(b[1]));
}

// ---------------------------------------------------------------------------
// float -> half (rne) converter, float4-wide
// ---------------------------------------------------------------------------
__global__ __launch_bounds__(256)
void f2h_kernel(const float* __restrict__ in, __half* __restrict__ out, int n4)
{
    for (int i = blockIdx.x * blockDim.x + threadIdx.x; i < n4; i += gridDim.x * blockDim.x) {
        float4 v = ((const float4*)in)[i];
        __half2 h01 = __floats2half2_rn(v.x, v.y);
        __half2 h23 = __floats2half2_rn(v.z, v.w);
        ((__half2*)out)[2 * i]     = h01;
        ((__half2*)out)[2 * i + 1] = h23;
    }
}

// ---------------------------------------------------------------------------
// FP16 tensor-core GEMM (m16n8k16, fp32 accum):
//   C = A @ B + bias (+ residual fp32) (+ relu); C fp32 or fp16.
// grid.z selects (B, bias, C) triple (QKV fusion); pass same ptr 3x otherwise.
// HEADED: B element (k,n) at ((n>>6)*K + k)*64 + (n&63)  (weights (H,D,DK))
// else:   B row-major [K,N]
// CTA tile 128x128, K-chunk 32, 8 warps (2x4 of 64x32), 3-stage cp.async.
// Smem per stage: A 128x32 halfs (XOR-swizzled 16B chunks: c^= (row>>1)&3),
//                 B  32x128 halfs (chunk cn ^= k&7 in low 3 bits).
// M,N multiples of 128; K multiple of 32.
// ---------------------------------------------------------------------------
#define HG_STAGE_BYTES 16384                     // (4096 + 4096) halfs
#define HG_SMEM_BYTES  (3 * HG_STAGE_BYTES)      // 49152

template <bool HEADED, bool RELU, bool RESID, bool OUTHALF>
__global__ __launch_bounds__(256, 2)
void hgemm(const __half* __restrict__ A,
           const __half* __restrict__ B0, const __half* __restrict__ B1,
           const __half* __restrict__ B2,
           const float* __restrict__ bi0, const float* __restrict__ bi1,
           const float* __restrict__ bi2,
           const float* __restrict__ R,
           void* C0, void* C1, void* C2,
           int M, int N, int K)
{
    extern __shared__ __align__(16) char smem[];
    uint32_t sbase;
    asm("{ .reg .u64 t; cvta.to.shared.u64 t, %1; cvt.u32.u64 %0, t; }"
        : "=r"(sbase) : "l"(smem));

    const int z = blockIdx.z;
    const __half* B = (z == 0) ? B0 : (z == 1) ? B1 : B2;
    const float* bias = (z == 0) ? bi0 : (z == 1) ? bi1 : bi2;
    void* Cv = (z == 0) ? C0 : (z == 1) ? C1 : C2;

    const int tid  = threadIdx.x;
    const int lane = tid & 31;
    const int warp = tid >> 5;
    const int warpM = (warp & 1) * 64;
    const int warpN = (warp >> 1) * 32;
    const int row_blk = blockIdx.y * 128;
    const int col_blk = blockIdx.x * 128;

    float acc[4][4][4];
#pragma unroll
    for (int i = 0; i < 4; i++)
#pragma unroll
        for (int j = 0; j < 4; j++)
#pragma unroll
            for (int r = 0; r < 4; r++) acc[i][j][r] = 0.f;

    const int nk = K >> 5;

    auto prefetch = [&](int kc, int st) {
        const uint32_t aS = sbase + st * HG_STAGE_BYTES;
        const uint32_t bS = aS + 8192;
#pragma unroll
        for (int i = 0; i < 2; i++) {
            int idx = tid + 256 * i;
            int row = idx >> 2, c = idx & 3;
            const __half* src = A + (size_t)(row_blk + row) * K + kc * 32 + c * 8;
            uint32_t dst = aS + (row * 32 + 8 * (c ^ ((row >> 1) & 3))) * 2;
            cp_async16(dst, src);
        }
#pragma unroll
        for (int i = 0; i < 2; i++) {
            int idx = tid + 256 * i;
            int k = idx >> 4, cn = idx & 15;
            int n = col_blk + cn * 8;
            const __half* src;
            if (HEADED) src = B + ((size_t)(n >> 6) * K + kc * 32 + k) * 64 + (n & 63);
            else        src = B + (size_t)(kc * 32 + k) * N + n;
            uint32_t dst = bS + (k * 128 + 8 * ((cn & 8) | ((cn ^ k) & 7))) * 2;
            cp_async16(dst, src);
        }
        cp_commit();
    };

    prefetch(0, 0);
    if (nk > 1) prefetch(1, 1);

    for (int kc = 0; kc < nk; kc++) {
        const int st = kc % 3;
        if (kc + 1 < nk) asm volatile("cp.async.wait_group 1;");
        else             asm volatile("cp.async.wait_group 0;");
        __syncthreads();
        if (kc + 2 < nk) prefetch(kc + 2, (kc + 2) % 3);

        const uint32_t aS = sbase + st * HG_STAGE_BYTES;
        const uint32_t bS = aS + 8192;
#pragma unroll
        for (int ks = 0; ks < 2; ks++) {
            uint32_t af[4][4], bf[4][2];
            const int rr = (lane & 7) + ((lane >> 3) & 1) * 8;
            const int cA = ks * 2 + (lane >> 4);
#pragma unroll
            for (int i = 0; i < 4; i++) {
                int r = warpM + i * 16 + rr;
                uint32_t addr = aS + (r * 32 + 8 * (cA ^ ((r >> 1) & 3))) * 2;
                ldsm_x4(af[i], addr);
            }
            const int kB = ks * 16 + (lane & 15);
#pragma unroll
            for (int j = 0; j < 4; j++) {
                int cn = (warpN + j * 8) >> 3;
                uint32_t addr = bS + (kB * 128 + 8 * ((cn & 8) | ((cn ^ kB) & 7))) * 2;
                ldsm_x2_t(bf[j], addr);
            }
#pragma unroll
            for (int i = 0; i < 4; i++)
#pragma unroll
                for (int j = 0; j < 4; j++)
                    mma_f16(acc[i][j], af[i], bf[j]);
        }
        __syncthreads();
    }

    // Epilogue: c0,c1 at (row, 2*lt), (row, 2*lt+1); c2,c3 at row+8.
    const int lg = lane >> 2;
    const int lt = lane & 3;
#pragma unroll
    for (int i = 0; i < 4; i++) {
#pragma unroll
        for (int j = 0; j < 4; j++) {
            int r0 = row_blk + warpM + i * 16 + lg;
            int c0 = col_blk + warpN + j * 8 + 2 * lt;
            float bv0 = bias[c0], bv1 = bias[c0 + 1];
            float v0 = acc[i][j][0] + bv0;
            float v1 = acc[i][j][1] + bv1;
            float v2 = acc[i][j][2] + bv0;
            float v3 = acc[i][j][3] + bv1;
            if (RESID) {
                const float2 r0v = *(const float2*)&R[(size_t)r0 * N + c0];
                const float2 r1v = *(const float2*)&R[(size_t)(r0 + 8) * N + c0];
                v0 += r0v.x; v1 += r0v.y; v2 += r1v.x; v3 += r1v.y;
            }
            if (RELU) {
                v0 = fmaxf(v0, 0.f); v1 = fmaxf(v1, 0.f);
                v2 = fmaxf(v2, 0.f); v3 = fmaxf(v3, 0.f);
            }
            if (OUTHALF) {
                __half* Ch = (__half*)Cv;
                *(__half2*)&Ch[(size_t)r0 * N + c0]       = __floats2half2_rn(v0, v1);
                *(__half2*)&Ch[(size_t)(r0 + 8) * N + c0] = __floats2half2_rn(v2, v3);
            } else {
                float* Cf = (float*)Cv;
                *(float2*)&Cf[(size_t)r0 * N + c0]       = make_float2(v0, v1);
                *(float2*)&Cf[(size_t)(r0 + 8) * N + c0] = make_float2(v2, v3);
            }
        }
    }
}

// ---------------------------------------------------------------------------
// Flash attention: q,k,v fp32 in (B, S, H*DK) concat layout; out = half.
// One CTA per (b, h, 64-row q tile). Online softmax over kv tiles of 64.
// kv length = *maskp (attn1) or S (maskp == nullptr).
// ---------------------------------------------------------------------------
#define AP 65   // pitch for transposed 64x64 tiles
#define VP 68   // pitch for row-major V tile (float4-aligned)
#define ATTN_SMEM_FLOATS (3 * 64 * AP + 64 * VP + 3 * 64)
#define ATTN_SMEM_BYTES (ATTN_SMEM_FLOATS * 4)

__global__ __launch_bounds__(256)
void attn_kernel(const float* __restrict__ q, const float* __restrict__ k,
                 const float* __restrict__ v, __half* __restrict__ out,
                 const int* __restrict__ maskp)
{
    extern __shared__ float sm[];
    float* Qs  = sm;                  // [64][AP] transposed: Qs[d*AP + r]
    float* Ks  = Qs + 64 * AP;        // [64][AP] transposed: Ks[d*AP + c]
    float* Ps  = Ks + 64 * AP;        // [64][AP] row-major scores/probs
    float* Vs  = Ps + 64 * AP;        // [64][VP] row-major: Vs[c*VP + d]
    float* mrow = Vs + 64 * VP;       // [64]
    float* lrow = mrow + 64;          // [64]
    float* srow = lrow + 64;          // [64]

    const int tid = threadIdx.x;
    const int tx = tid & 15;          // col group
    const int ty = tid >> 4;          // row group
    const int qt = blockIdx.x;
    const int h  = blockIdx.y;
    const int b  = blockIdx.z;

    int kvlen = maskp ? *maskp : SSEQ;
    if (kvlen > SSEQ) kvlen = SSEQ;
    if (kvlen < 1) kvlen = 1;

    const float* qb = q + ((size_t)(b * SSEQ) + qt * 64) * DDIM + h * DKK;
    const float* kb = k + (size_t)(b * SSEQ) * DDIM + h * DKK;
    const float* vb = v + (size_t)(b * SSEQ) * DDIM + h * DKK;

    // load Q tile (transposed)
#pragma unroll
    for (int c = 0; c < 4; c++) {
        int idx = tid + c * 256;
        int r = idx >> 4;
        int d0 = (idx & 15) * 4;
        float4 t = *(const float4*)&qb[(size_t)r * DDIM + d0];
        Qs[(d0 + 0) * AP + r] = t.x;
        Qs[(d0 + 1) * AP + r] = t.y;
        Qs[(d0 + 2) * AP + r] = t.z;
        Qs[(d0 + 3) * AP + r] = t.w;
    }
    if (tid < 64) { mrow[tid] = -1e30f; lrow[tid] = 0.f; }

    float O[4][4];
#pragma unroll
    for (int i = 0; i < 4; i++)
#pragma unroll
        for (int j = 0; j < 4; j++) O[i][j] = 0.f;

    const int nt = (kvlen + 63) >> 6;
    for (int t = 0; t < nt; t++) {
        __syncthreads();   // previous-iteration consumers of Ks/Vs done
        const float* kt = kb + (size_t)(t * 64) * DDIM;
        const float* vt = vb + (size_t)(t * 64) * DDIM;
#pragma unroll
        for (int c = 0; c < 4; c++) {
            int idx = tid + c * 256;
            int r = idx >> 4;
            int d0 = (idx & 15) * 4;
            float4 tk = *(const float4*)&kt[(size_t)r * DDIM + d0];
            Ks[(d0 + 0) * AP + r] = tk.x;
            Ks[(d0 + 1) * AP + r] = tk.y;
            Ks[(d0 + 2) * AP + r] = tk.z;
            Ks[(d0 + 3) * AP + r] = tk.w;
            float4 tv = *(const float4*)&vt[(size_t)r * DDIM + d0];
            *(float4*)&Vs[r * VP + d0] = tv;
        }
        __syncthreads();

        // scores: s = (Q K^T) * 1/sqrt(64)
        float sacc[4][4];
#pragma unroll
        for (int i = 0; i < 4; i++)
#pragma unroll
            for (int j = 0; j < 4; j++) sacc[i][j] = 0.f;
#pragma unroll 8
        for (int d = 0; d < 64; d++) {
            float aq[4], bk[4];
#pragma unroll
            for (int i = 0; i < 4; i++) aq[i] = Qs[d * AP + ty * 4 + i];
#pragma unroll
            for (int j = 0; j < 4; j++) bk[j] = Ks[d * AP + tx * 4 + j];
#pragma unroll
            for (int i = 0; i < 4; i++)
#pragma unroll
                for (int j = 0; j < 4; j++) sacc[i][j] += aq[i] * bk[j];
        }
        const int cbase = t * 64 + tx * 4;
#pragma unroll
        for (int i = 0; i < 4; i++)
#pragma unroll
            for (int j = 0; j < 4; j++) {
                float val = (cbase + j < kvlen) ? sacc[i][j] * 0.125f : -1e30f;
                Ps[(ty * 4 + i) * AP + tx * 4 + j] = val;
            }
        __syncthreads();

        // online softmax: 4 threads per row (tid>>2 = row, tid&3 = quarter)
        {
            const int row = tid >> 2;
            const int tq = tid & 3;
            float* pr = &Ps[row * AP + tq * 16];
            float mt = -1e30f;
#pragma unroll
            for (int c = 0; c < 16; c++) mt = fmaxf(mt, pr[c]);
            mt = fmaxf(mt, __shfl_xor_sync(0xffffffffu, mt, 1));
            mt = fmaxf(mt, __shfl_xor_sync(0xffffffffu, mt, 2));
            float mo = mrow[row];
            float mn = fmaxf(mo, mt);
            float sum = 0.f;
#pragma unroll
            for (int c = 0; c < 16; c++) {
                float p = __expf(pr[c] - mn);
                pr[c] = p;
                sum += p;
            }
            sum += __shfl_xor_sync(0xffffffffu, sum, 1);
            sum += __shfl_xor_sync(0xffffffffu, sum, 2);
            if (tq == 0) {
                float sc = __expf(mo - mn);
                lrow[row] = lrow[row] * sc + sum;
                mrow[row] = mn;
                srow[row] = sc;
            }
        }
        __syncthreads();

        // rescale O, accumulate O += P @ V
        float sci[4];
#pragma unroll
        for (int i = 0; i < 4; i++) sci[i] = srow[ty * 4 + i];
#pragma unroll
        for (int i = 0; i < 4; i++)
#pragma unroll
            for (int j = 0; j < 4; j++) O[i][j] *= sci[i];
#pragma unroll 8
        for (int c = 0; c < 64; c++) {
            float pv[4];
#pragma unroll
            for (int i = 0; i < 4; i++) pv[i] = Ps[(ty * 4 + i) * AP + c];
            float4 vv = *(const float4*)&Vs[c * VP + tx * 4];
#pragma unroll
            for (int i = 0; i < 4; i++) {
                O[i][0] += pv[i] * vv.x;
                O[i][1] += pv[i] * vv.y;
                O[i][2] += pv[i] * vv.z;
                O[i][3] += pv[i] * vv.w;
            }
        }
    }
    __syncthreads();

    __half* ob = out + ((size_t)(b * SSEQ) + qt * 64) * DDIM + h * DKK;
#pragma unroll
    for (int i = 0; i < 4; i++) {
        float inv = 1.f / lrow[ty * 4 + i];
        __half2 p0 = __floats2half2_rn(O[i][0] * inv, O[i][1] * inv);
        __half2 p1 = __floats2half2_rn(O[i][2] * inv, O[i][3] * inv);
        __half2* dst = (__half2*)&ob[(size_t)(ty * 4 + i) * DDIM + tx * 4];
        dst[0] = p0;
        dst[1] = p1;
    }
}

// ---------------------------------------------------------------------------
// BatchNorm over axes (B, D) per s (channel axis = 1, S==D==1024).
// Writes half output (if outh) and/or float output (if outf).
// ---------------------------------------------------------------------------
__global__ __launch_bounds__(256)
void bn_kernel(const float* __restrict__ in, const float* __restrict__ g,
               const float* __restrict__ be, __half* __restrict__ outh,
               float* __restrict__ outf)
{
    __shared__ float s_sum[256];
    __shared__ float s_sq[256];
    __shared__ float s_mean, s_rs;

    const int s = blockIdx.x;
    const int tid = threadIdx.x;

    float sum = 0.f, sq = 0.f;
#pragma unroll
    for (int b = 0; b < BB; b++) {
        const float* row = in + ((size_t)b * SSEQ + s) * DDIM;
        for (int d = tid; d < DDIM; d += 256) {
            float x = row[d];
            sum += x;
            sq += x * x;
        }
    }
    s_sum[tid] = sum;
    s_sq[tid] = sq;
    __syncthreads();
    for (int o = 128; o > 0; o >>= 1) {
        if (tid < o) { s_sum[tid] += s_sum[tid + o]; s_sq[tid] += s_sq[tid + o]; }
        __syncthreads();
    }
    if (tid == 0) {
        const float inv_n = 1.f / (BB * DDIM);
        float mean = s_sum[0] * inv_n;
        float var = s_sq[0] * inv_n - mean * mean;
        s_mean = mean;
        s_rs = rsqrtf(var + 1e-5f);
    }
    __syncthreads();
    const float gg = g[s], bb2 = be[s], mean = s_mean, rs = s_rs;
#pragma unroll
    for (int b = 0; b < BB; b++) {
        const float* row = in + ((size_t)b * SSEQ + s) * DDIM;
        const size_t off = ((size_t)b * SSEQ + s) * DDIM;
        for (int d = tid; d < DDIM; d += 256) {
            float val = (row[d] - mean) * rs * gg + bb2;
            if (outh) outh[off + d] = __float2half_rn(val);
            if (outf) outf[off + d] = val;
        }
    }
}

// ---------------------------------------------------------------------------
// Host orchestration
// ---------------------------------------------------------------------------
extern "C" void kernel_launch(void* const* d_in, const int* in_sizes, int n_in,
                              void* d_out, int out_size)
{
    const float* x   = (const float*)d_in[0];
    const float* Wq1 = (const float*)d_in[1];
    const float* bq1 = (const float*)d_in[2];
    const float* Wk1 = (const float*)d_in[3];
    const float* bk1 = (const float*)d_in[4];
    const float* Wv1 = (const float*)d_in[5];
    const float* bv1 = (const float*)d_in[6];
    const float* Wo1 = (const float*)d_in[7];
    const float* bo1 = (const float*)d_in[8];
    const float* Wq2 = (const float*)d_in[9];
    const float* bq2 = (const float*)d_in[10];
    const float* Wk2 = (const float*)d_in[11];
    const float* bk2 = (const float*)d_in[12];
    const float* Wv2 = (const float*)d_in[13];
    const float* bv2 = (const float*)d_in[14];
    const float* Wo2 = (const float*)d_in[15];
    const float* bo2 = (const float*)d_in[16];
    const float* g1  = (const float*)d_in[17];
    const float* be1 = (const float*)d_in[18];
    const float* g2  = (const float*)d_in[19];
    const float* be2 = (const float*)d_in[20];
    const float* g3  = (const float*)d_in[21];
    const float* be3 = (const float*)d_in[22];
    const float* W1  = (const float*)d_in[23];
    const float* bf1 = (const float*)d_in[24];
    const float* W2  = (const float*)d_in[25];
    const float* bf2 = (const float*)d_in[26];
    const int*   maskp = (const int*)d_in[27];

    float *q, *k, *v, *tmp, *x1f, *hf;
    __half *xh, *ah, *x1h, *yh, *hh, *hidh;
    __half *wq1, *wk1, *wv1, *wo1, *wq2, *wk2, *wv2, *wo2, *w1h, *w2h;
    cudaGetSymbolAddress((void**)&q,    g_q);
    cudaGetSymbolAddress((void**)&k,    g_k);
    cudaGetSymbolAddress((void**)&v,    g_v);
    cudaGetSymbolAddress((void**)&tmp,  g_tmp);
    cudaGetSymbolAddress((void**)&x1f,  g_x1f);
    cudaGetSymbolAddress((void**)&hf,   g_hf);
    cudaGetSymbolAddress((void**)&xh,   g_xh);
    cudaGetSymbolAddress((void**)&ah,   g_ah);
    cudaGetSymbolAddress((void**)&x1h,  g_x1h);
    cudaGetSymbolAddress((void**)&yh,   g_yh);
    cudaGetSymbolAddress((void**)&hh,   g_hh);
    cudaGetSymbolAddress((void**)&hidh, g_hidh);
    cudaGetSymbolAddress((void**)&wq1,  g_wq1);
    cudaGetSymbolAddress((void**)&wk1,  g_wk1);
    cudaGetSymbolAddress((void**)&wv1,  g_wv1);
    cudaGetSymbolAddress((void**)&wo1,  g_wo1);
    cudaGetSymbolAddress((void**)&wq2,  g_wq2);
    cudaGetSymbolAddress((void**)&wk2,  g_wk2);
    cudaGetSymbolAddress((void**)&wv2,  g_wv2);
    cudaGetSymbolAddress((void**)&wo2,  g_wo2);
    cudaGetSymbolAddress((void**)&w1h,  g_w1h);
    cudaGetSymbolAddress((void**)&w2h,  g_w2h);

    cudaFuncSetAttribute(attn_kernel, cudaFuncAttributeMaxDynamicSharedMemorySize,
                         ATTN_SMEM_BYTES);
    cudaFuncSetAttribute(hgemm<true, false, false, false>,
                         cudaFuncAttributeMaxDynamicSharedMemorySize, HG_SMEM_BYTES);
    cudaFuncSetAttribute(hgemm<false, false, true, false>,
                         cudaFuncAttributeMaxDynamicSharedMemorySize, HG_SMEM_BYTES);
    cudaFuncSetAttribute(hgemm<false, true, false, true>,
                         cudaFuncAttributeMaxDynamicSharedMemorySize, HG_SMEM_BYTES);

    // ---- convert input + weights to fp16 (rne) ----
    {
        const dim3 rb(256);
        f2h_kernel<<<512,  rb>>>(x,   xh,  (MM * DDIM) / 4);
        f2h_kernel<<<1024, rb>>>(Wq1, wq1, QKVW / 4);
        f2h_kernel<<<1024, rb>>>(Wk1, wk1, QKVW / 4);
        f2h_kernel<<<1024, rb>>>(Wv1, wv1, QKVW / 4);
        f2h_kernel<<<1024, rb>>>(Wo1, wo1, OW / 4);
        f2h_kernel<<<1024, rb>>>(Wq2, wq2, QKVW / 4);
        f2h_kernel<<<1024, rb>>>(Wk2, wk2, QKVW / 4);
        f2h_kernel<<<1024, rb>>>(Wv2, wv2, QKVW / 4);
        f2h_kernel<<<1024, rb>>>(Wo2, wo2, OW / 4);
        f2h_kernel<<<2048, rb>>>(W1,  w1h, W1SZ / 4);
        f2h_kernel<<<2048, rb>>>(W2,  w2h, W1SZ / 4);
    }

    const dim3 blk(256);
    const dim3 gQKV(DDIM / 128, MM / 128, 3);  // fused q,k,v
    const dim3 gD(DDIM / 128, MM / 128, 1);
    const dim3 gF(FFD / 128, MM / 128, 1);
    const dim3 gAttn(SSEQ / 64, HH, BB);

    const __half* hinh = xh;
    const float*  hres = x;
    for (int l = 0; l < LNUM; l++) {
        const size_t wOff  = (size_t)l * HH * DDIM * DKK;
        const size_t bOff  = (size_t)l * HH * DKK;
        const size_t woOff = (size_t)l * DDIM * DDIM;
        const size_t dOff  = (size_t)l * DDIM;
        const size_t w1Off = (size_t)l * DDIM * FFD;
        const size_t f1Off = (size_t)l * FFD;
        const size_t w2Off = (size_t)l * FFD * DDIM;

        // ---- masked self-attention ----
        hgemm<true, false, false, false><<<gQKV, blk, HG_SMEM_BYTES>>>(
            hinh, wq1 + wOff, wk1 + wOff, wv1 + wOff,
            bq1 + bOff, bk1 + bOff, bv1 + bOff,
            nullptr, q, k, v, MM, DDIM, DDIM);
        attn_kernel<<<gAttn, blk, ATTN_SMEM_BYTES>>>(q, k, v, ah, maskp);
        hgemm<false, false, true, false><<<gD, blk, HG_SMEM_BYTES>>>(
            ah, wo1 + woOff, wo1 + woOff, wo1 + woOff,
            bo1 + dOff, bo1 + dOff, bo1 + dOff,
            hres, tmp, tmp, tmp, MM, DDIM, DDIM);
        bn_kernel<<<SSEQ, blk>>>(tmp, g1 + dOff, be1 + dOff, x1h, x1f);

        // ---- second (unmasked) self-attention; residual from block input ----
        hgemm<true, false, false, false><<<gQKV, blk, HG_SMEM_BYTES>>>(
            x1h, wq2 + wOff, wk2 + wOff, wv2 + wOff,
            bq2 + bOff, bk2 + bOff, bv2 + bOff,
            nullptr, q, k, v, MM, DDIM, DDIM);
        attn_kernel<<<gAttn, blk, ATTN_SMEM_BYTES>>>(q, k, v, ah, nullptr);
        hgemm<false, false, true, false><<<gD, blk, HG_SMEM_BYTES>>>(
            ah, wo2 + woOff, wo2 + woOff, wo2 + woOff,
            bo2 + dOff, bo2 + dOff, bo2 + dOff,
            hres, tmp, tmp, tmp, MM, DDIM, DDIM);
        bn_kernel<<<SSEQ, blk>>>(tmp, g2 + dOff, be2 + dOff, yh, nullptr);

        // ---- FFN; residual from x1 ----
        hgemm<false, true, false, true><<<gF, blk, HG_SMEM_BYTES>>>(
            yh, w1h + w1Off, w1h + w1Off, w1h + w1Off,
            bf1 + f1Off, bf1 + f1Off, bf1 + f1Off,
            nullptr, hidh, hidh, hidh, MM, FFD, DDIM);
        hgemm<false, false, true, false><<<gD, blk, HG_SMEM_BYTES>>>(
            hidh, w2h + w2Off, w2h + w2Off, w2h + w2Off,
            bf2 + dOff, bf2 + dOff, bf2 + dOff,
            x1f, tmp, tmp, tmp, MM, DDIM, FFD);

        if (l == LNUM - 1) {
            bn_kernel<<<SSEQ, blk>>>(tmp, g3 + dOff, be3 + dOff, nullptr, (float*)d_out);
        } else {
            bn_kernel<<<SSEQ, blk>>>(tmp, g3 + dOff, be3 + dOff, hh, hf);
        }
        hinh = hh;
        hres = hf;
    }
}